// round 1
// baseline (speedup 1.0000x reference)
#include <cuda_runtime.h>

// Problem constants: B=2, T=2048, C=1024, H=16, D=64
#define TT 2048
#define CC 1024

// Scratch (allocation-free rule: __device__ globals)
__device__ float g_qkv[2 * 2048 * 3 * 1024];  // [B,T,3,H,D]
__device__ float g_y[2 * 2048 * 1024];        // [B,T,H,D]

// ---------------------------------------------------------------------------
// Tiled SGEMM with bias: C[M,N] = A[M,K] @ B[K,N] + bias[N]
// A,B,C row-major. M,N multiples of 128, K multiple of 8.
// ---------------------------------------------------------------------------
#define BM 128
#define BN 128
#define BKK 8
#define TM 8
#define TN 8

__global__ __launch_bounds__(256, 2)
void sgemm_bias_kernel(const float* __restrict__ A, const float* __restrict__ Bw,
                       const float* __restrict__ bias, float* __restrict__ Cout,
                       int M, int N, int K) {
    __shared__ float As[BKK][BM];
    __shared__ float Bs[BKK][BN];
    const int tid = threadIdx.x;
    const int br = blockIdx.y * BM;
    const int bc = blockIdx.x * BN;
    const int tr = (tid / 16) * TM;
    const int tc = (tid % 16) * TN;

    const int a_row = tid >> 1;
    const int a_col = (tid & 1) * 4;
    const int b_row = tid >> 5;
    const int b_col = (tid & 31) * 4;

    const float* Ap = A + (long)(br + a_row) * K + a_col;
    const float* Bp = Bw + (long)b_row * N + bc + b_col;

    float acc[TM][TN];
#pragma unroll
    for (int i = 0; i < TM; i++)
#pragma unroll
        for (int j = 0; j < TN; j++) acc[i][j] = 0.f;

    for (int k0 = 0; k0 < K; k0 += BKK) {
        float4 av = *(const float4*)(Ap + k0);
        As[a_col + 0][a_row] = av.x;
        As[a_col + 1][a_row] = av.y;
        As[a_col + 2][a_row] = av.z;
        As[a_col + 3][a_row] = av.w;
        float4 bv = *(const float4*)(Bp + (long)k0 * N);
        *(float4*)&Bs[b_row][b_col] = bv;
        __syncthreads();
#pragma unroll
        for (int k = 0; k < BKK; k++) {
            float ar[TM], brg[TN];
            *(float4*)&ar[0]  = *(const float4*)&As[k][tr];
            *(float4*)&ar[4]  = *(const float4*)&As[k][tr + 4];
            *(float4*)&brg[0] = *(const float4*)&Bs[k][tc];
            *(float4*)&brg[4] = *(const float4*)&Bs[k][tc + 4];
#pragma unroll
            for (int i = 0; i < TM; i++)
#pragma unroll
                for (int j = 0; j < TN; j++)
                    acc[i][j] += ar[i] * brg[j];
        }
        __syncthreads();
    }

    float bb[TN];
    *(float4*)&bb[0] = *(const float4*)(bias + bc + tc);
    *(float4*)&bb[4] = *(const float4*)(bias + bc + tc + 4);
#pragma unroll
    for (int i = 0; i < TM; i++) {
        float* crow = Cout + (long)(br + tr + i) * N + bc + tc;
        float4 o0, o1;
        o0.x = acc[i][0] + bb[0]; o0.y = acc[i][1] + bb[1];
        o0.z = acc[i][2] + bb[2]; o0.w = acc[i][3] + bb[3];
        o1.x = acc[i][4] + bb[4]; o1.y = acc[i][5] + bb[5];
        o1.z = acc[i][6] + bb[6]; o1.w = acc[i][7] + bb[7];
        *(float4*)(crow)     = o0;
        *(float4*)(crow + 4) = o1;
    }
}

// ---------------------------------------------------------------------------
// Fused per-head RMSNorm + RoPE on q and k slots of g_qkv (in place).
// One CTA per (b,t). 256 threads, 4 elements each. Head = 64 elems = 16 threads.
// ---------------------------------------------------------------------------
__global__ __launch_bounds__(256)
void norm_rope_kernel(float* __restrict__ qkv,
                      const float* __restrict__ cosb,
                      const float* __restrict__ sinb) {
    __shared__ float qn[1024];
    __shared__ float kn[1024];
    const int bt = blockIdx.x;
    const int t = bt & (TT - 1);
    const int tid = threadIdx.x;
    float* qrow = qkv + (long)bt * 3072;
    float* krow = qrow + 1024;

    float4 qv = *(const float4*)(qrow + tid * 4);
    float4 kv = *(const float4*)(krow + tid * 4);
    float qs = qv.x * qv.x + qv.y * qv.y + qv.z * qv.z + qv.w * qv.w;
    float ks = kv.x * kv.x + kv.y * kv.y + kv.z * kv.z + kv.w * kv.w;
#pragma unroll
    for (int o = 8; o > 0; o >>= 1) {
        qs += __shfl_xor_sync(0xffffffffu, qs, o);
        ks += __shfl_xor_sync(0xffffffffu, ks, o);
    }
    const float qsc = rsqrtf(qs * (1.f / 64.f) + 1.1920929e-07f);
    const float ksc = rsqrtf(ks * (1.f / 64.f) + 1.1920929e-07f);
    float4 qn4 = make_float4(qv.x * qsc, qv.y * qsc, qv.z * qsc, qv.w * qsc);
    float4 kn4 = make_float4(kv.x * ksc, kv.y * ksc, kv.z * ksc, kv.w * ksc);
    *(float4*)&qn[tid * 4] = qn4;
    *(float4*)&kn[tid * 4] = kn4;
    __syncthreads();

    const int i = tid * 4;
    const int d = i & 63;
    const int base = i - d;
    float4 cv = *(const float4*)(cosb + t * 64 + d);
    float4 sv = *(const float4*)(sinb + t * 64 + d);
    float4 rq, rk;
    if (d < 32) {
        float4 pq = *(const float4*)&qn[base + d + 32];
        float4 pk = *(const float4*)&kn[base + d + 32];
        rq = make_float4(-pq.x, -pq.y, -pq.z, -pq.w);
        rk = make_float4(-pk.x, -pk.y, -pk.z, -pk.w);
    } else {
        rq = *(const float4*)&qn[base + d - 32];
        rk = *(const float4*)&kn[base + d - 32];
    }
    float4 oq, ok;
    oq.x = qn4.x * cv.x + rq.x * sv.x;  oq.y = qn4.y * cv.y + rq.y * sv.y;
    oq.z = qn4.z * cv.z + rq.z * sv.z;  oq.w = qn4.w * cv.w + rq.w * sv.w;
    ok.x = kn4.x * cv.x + rk.x * sv.x;  ok.y = kn4.y * cv.y + rk.y * sv.y;
    ok.z = kn4.z * cv.z + rk.z * sv.z;  ok.w = kn4.w * cv.w + rk.w * sv.w;
    *(float4*)(qrow + i) = oq;
    *(float4*)(krow + i) = ok;
}

// ---------------------------------------------------------------------------
// Flash-style causal attention, fp32.
// CTA per (qb, h, b): 64 queries. 256 threads: row = tid/4 (query row),
// cg = tid%4 (16-wide column/dim group).
// K is staged transposed (d-major) in smem for conflict-free S; V natural.
// ---------------------------------------------------------------------------
#define PAD 68
#define ATT_SMEM (3 * 64 * PAD * 4)

__global__ __launch_bounds__(256)
void attn_kernel(const float* __restrict__ qkv, float* __restrict__ y) {
    extern __shared__ float sm[];
    float* Qs  = sm;
    float* KVs = sm + 64 * PAD;
    float* Ps  = sm + 2 * 64 * PAD;
    const int qb = blockIdx.x, h = blockIdx.y, b = blockIdx.z;
    const int tid = threadIdx.x;
    const int row = tid >> 2, cg = tid & 3;

    // Load Q tile (pre-scaled by 1/sqrt(D))
    {
        const float* src = qkv + ((long)(b * TT + qb * 64 + row) * 3) * 1024 + h * 64 + cg * 16;
#pragma unroll
        for (int v4 = 0; v4 < 4; v4++) {
            float4 val = *(const float4*)(src + v4 * 4);
            val.x *= 0.125f; val.y *= 0.125f; val.z *= 0.125f; val.w *= 0.125f;
            *(float4*)&Qs[row * PAD + cg * 16 + v4 * 4] = val;
        }
    }

    float m = -3.0e38f, l = 0.f;
    float Oa[16];
#pragma unroll
    for (int i = 0; i < 16; i++) Oa[i] = 0.f;

    for (int kb = 0; kb <= qb; kb++) {
        __syncthreads();  // prev-iter readers done (and Qs ready on iter 0)
        // Load K tile transposed: KVs[d][col]
        {
            const float* src = qkv + ((long)(b * TT + kb * 64 + row) * 3 + 1) * 1024 + h * 64 + cg * 16;
#pragma unroll
            for (int v4 = 0; v4 < 4; v4++) {
                float4 val = *(const float4*)(src + v4 * 4);
                int d0 = cg * 16 + v4 * 4;
                KVs[(d0 + 0) * PAD + row] = val.x;
                KVs[(d0 + 1) * PAD + row] = val.y;
                KVs[(d0 + 2) * PAD + row] = val.z;
                KVs[(d0 + 3) * PAD + row] = val.w;
            }
        }
        __syncthreads();

        float s[16];
#pragma unroll
        for (int j = 0; j < 16; j++) s[j] = 0.f;
#pragma unroll 4
        for (int d = 0; d < 64; d++) {
            float qd = Qs[row * PAD + d];
            const float4* kr = (const float4*)&KVs[d * PAD + cg * 16];
            float4 k0 = kr[0], k1 = kr[1], k2 = kr[2], k3 = kr[3];
            s[0]  += qd * k0.x; s[1]  += qd * k0.y; s[2]  += qd * k0.z; s[3]  += qd * k0.w;
            s[4]  += qd * k1.x; s[5]  += qd * k1.y; s[6]  += qd * k1.z; s[7]  += qd * k1.w;
            s[8]  += qd * k2.x; s[9]  += qd * k2.y; s[10] += qd * k2.z; s[11] += qd * k2.w;
            s[12] += qd * k3.x; s[13] += qd * k3.y; s[14] += qd * k3.z; s[15] += qd * k3.w;
        }
        if (kb == qb) {
#pragma unroll
            for (int j = 0; j < 16; j++)
                if (cg * 16 + j > row) s[j] = -3.0e38f;
        }
        float smax = s[0];
#pragma unroll
        for (int j = 1; j < 16; j++) smax = fmaxf(smax, s[j]);
        smax = fmaxf(smax, __shfl_xor_sync(0xffffffffu, smax, 1));
        smax = fmaxf(smax, __shfl_xor_sync(0xffffffffu, smax, 2));
        float mnew = fmaxf(m, smax);
        float psum = 0.f;
#pragma unroll
        for (int j = 0; j < 16; j++) { s[j] = __expf(s[j] - mnew); psum += s[j]; }
        psum += __shfl_xor_sync(0xffffffffu, psum, 1);
        psum += __shfl_xor_sync(0xffffffffu, psum, 2);
        float alpha = __expf(m - mnew);
        l = l * alpha + psum;
        m = mnew;
#pragma unroll
        for (int i = 0; i < 16; i++) Oa[i] *= alpha;
#pragma unroll
        for (int v4 = 0; v4 < 4; v4++)
            *(float4*)&Ps[row * PAD + cg * 16 + v4 * 4] =
                make_float4(s[v4 * 4], s[v4 * 4 + 1], s[v4 * 4 + 2], s[v4 * 4 + 3]);
        __syncthreads();  // P written, K reads done → KVs reusable

        // Load V tile natural: KVs[col][d]
        {
            const float* src = qkv + ((long)(b * TT + kb * 64 + row) * 3 + 2) * 1024 + h * 64 + cg * 16;
#pragma unroll
            for (int v4 = 0; v4 < 4; v4++)
                *(float4*)&KVs[row * PAD + cg * 16 + v4 * 4] = *(const float4*)(src + v4 * 4);
        }
        __syncthreads();

#pragma unroll 2
        for (int col = 0; col < 64; col++) {
            float p = Ps[row * PAD + col];
            const float4* vv = (const float4*)&KVs[col * PAD + cg * 16];
            float4 v0 = vv[0], v1 = vv[1], v2 = vv[2], v3 = vv[3];
            Oa[0]  += p * v0.x; Oa[1]  += p * v0.y; Oa[2]  += p * v0.z; Oa[3]  += p * v0.w;
            Oa[4]  += p * v1.x; Oa[5]  += p * v1.y; Oa[6]  += p * v1.z; Oa[7]  += p * v1.w;
            Oa[8]  += p * v2.x; Oa[9]  += p * v2.y; Oa[10] += p * v2.z; Oa[11] += p * v2.w;
            Oa[12] += p * v3.x; Oa[13] += p * v3.y; Oa[14] += p * v3.z; Oa[15] += p * v3.w;
        }
    }

    const float inv = 1.0f / l;
    float* dst = y + (long)(b * TT + qb * 64 + row) * 1024 + h * 64 + cg * 16;
#pragma unroll
    for (int v4 = 0; v4 < 4; v4++) {
        float4 o = make_float4(Oa[v4 * 4] * inv, Oa[v4 * 4 + 1] * inv,
                               Oa[v4 * 4 + 2] * inv, Oa[v4 * 4 + 3] * inv);
        *(float4*)(dst + v4 * 4) = o;
    }
}

// ---------------------------------------------------------------------------
extern "C" void kernel_launch(void* const* d_in, const int* in_sizes, int n_in,
                              void* d_out, int out_size) {
    const float* x      = (const float*)d_in[0];
    const float* cosb   = (const float*)d_in[1];
    const float* sinb   = (const float*)d_in[2];
    const float* W_attn = (const float*)d_in[3];
    const float* b_attn = (const float*)d_in[4];
    const float* W_proj = (const float*)d_in[5];
    const float* b_proj = (const float*)d_in[6];
    float* out = (float*)d_out;

    float *qkv, *y;
    cudaGetSymbolAddress((void**)&qkv, g_qkv);
    cudaGetSymbolAddress((void**)&y, g_y);

    // 1) QKV GEMM: [4096,1024] @ [1024,3072] + bias
    sgemm_bias_kernel<<<dim3(3072 / BN, 4096 / BM), 256>>>(x, W_attn, b_attn, qkv, 4096, 3072, 1024);

    // 2) per-head RMSNorm + RoPE on q,k (in place)
    norm_rope_kernel<<<2 * TT, 256>>>(qkv, cosb, sinb);

    // 3) causal attention
    cudaFuncSetAttribute(attn_kernel, cudaFuncAttributeMaxDynamicSharedMemorySize, ATT_SMEM);
    attn_kernel<<<dim3(TT / 64, 16, 2), 256, ATT_SMEM>>>(qkv, y);

    // 4) output projection: [4096,1024] @ [1024,1024] + bias
    sgemm_bias_kernel<<<dim3(1024 / BN, 4096 / BM), 256>>>(y, W_proj, b_proj, out, 4096, 1024, 1024);
}

// round 3
// speedup vs baseline: 2.3970x; 2.3970x over previous
#include <cuda_runtime.h>

// Problem constants: B=2, T=2048, C=1024, H=16, D=64
#define TT 2048

// Scratch (allocation-free rule: __device__ globals)
__device__ float g_qkv[2 * 2048 * 3 * 1024];  // [B,T,3,H,D]
__device__ float g_y[2 * 2048 * 1024];        // [B,T,H,D]

// ---------------------------------------------------------------------------
// Tiled SGEMM with bias: C[M,N] = A[M,K] @ B[K,N] + bias[N]
// BK=16, 128x128 block, 8x8 microtile.
// ---------------------------------------------------------------------------
#define BM 128
#define BN 128
#define BKK 16
#define TM 8
#define TN 8

__global__ __launch_bounds__(256, 2)
void sgemm_bias_kernel(const float* __restrict__ A, const float* __restrict__ Bw,
                       const float* __restrict__ bias, float* __restrict__ Cout,
                       int M, int N, int K) {
    __shared__ float As[BKK][BM];
    __shared__ float Bs[BKK][BN];
    const int tid = threadIdx.x;
    const int br = blockIdx.y * BM;
    const int bc = blockIdx.x * BN;
    const int tr = (tid / 16) * TM;
    const int tc = (tid % 16) * TN;

    const int a_row = tid >> 1;          // 0..127
    const int a_col = (tid & 1) * 4;     // 0 or 4 (+8 for second vec)
    const int b_row = tid >> 5;          // 0..7 (+8 for second vec)
    const int b_col = (tid & 31) * 4;

    const float* Ap = A + (long)(br + a_row) * K + a_col;
    const float* Bp = Bw + (long)b_row * N + bc + b_col;

    float acc[TM][TN];
#pragma unroll
    for (int i = 0; i < TM; i++)
#pragma unroll
        for (int j = 0; j < TN; j++) acc[i][j] = 0.f;

    for (int k0 = 0; k0 < K; k0 += BKK) {
        float4 av0 = *(const float4*)(Ap + k0);
        float4 av1 = *(const float4*)(Ap + k0 + 8);
        As[a_col + 0][a_row] = av0.x;
        As[a_col + 1][a_row] = av0.y;
        As[a_col + 2][a_row] = av0.z;
        As[a_col + 3][a_row] = av0.w;
        As[a_col + 8][a_row] = av1.x;
        As[a_col + 9][a_row] = av1.y;
        As[a_col + 10][a_row] = av1.z;
        As[a_col + 11][a_row] = av1.w;
        float4 bv0 = *(const float4*)(Bp + (long)k0 * N);
        float4 bv1 = *(const float4*)(Bp + (long)(k0 + 8) * N);
        *(float4*)&Bs[b_row][b_col] = bv0;
        *(float4*)&Bs[b_row + 8][b_col] = bv1;
        __syncthreads();
#pragma unroll
        for (int k = 0; k < BKK; k++) {
            float ar[TM], brg[TN];
            *(float4*)&ar[0]  = *(const float4*)&As[k][tr];
            *(float4*)&ar[4]  = *(const float4*)&As[k][tr + 4];
            *(float4*)&brg[0] = *(const float4*)&Bs[k][tc];
            *(float4*)&brg[4] = *(const float4*)&Bs[k][tc + 4];
#pragma unroll
            for (int i = 0; i < TM; i++)
#pragma unroll
                for (int j = 0; j < TN; j++)
                    acc[i][j] += ar[i] * brg[j];
        }
        __syncthreads();
    }

    float bb[TN];
    *(float4*)&bb[0] = *(const float4*)(bias + bc + tc);
    *(float4*)&bb[4] = *(const float4*)(bias + bc + tc + 4);
#pragma unroll
    for (int i = 0; i < TM; i++) {
        float* crow = Cout + (long)(br + tr + i) * N + bc + tc;
        float4 o0, o1;
        o0.x = acc[i][0] + bb[0]; o0.y = acc[i][1] + bb[1];
        o0.z = acc[i][2] + bb[2]; o0.w = acc[i][3] + bb[3];
        o1.x = acc[i][4] + bb[4]; o1.y = acc[i][5] + bb[5];
        o1.z = acc[i][6] + bb[6]; o1.w = acc[i][7] + bb[7];
        *(float4*)(crow)     = o0;
        *(float4*)(crow + 4) = o1;
    }
}

// ---------------------------------------------------------------------------
// Fused per-head RMSNorm + RoPE on q and k slots of g_qkv (in place).
// ---------------------------------------------------------------------------
__global__ __launch_bounds__(256)
void norm_rope_kernel(float* __restrict__ qkv,
                      const float* __restrict__ cosb,
                      const float* __restrict__ sinb) {
    __shared__ float qn[1024];
    __shared__ float kn[1024];
    const int bt = blockIdx.x;
    const int t = bt & (TT - 1);
    const int tid = threadIdx.x;
    float* qrow = qkv + (long)bt * 3072;
    float* krow = qrow + 1024;

    float4 qv = *(const float4*)(qrow + tid * 4);
    float4 kv = *(const float4*)(krow + tid * 4);
    float qs = qv.x * qv.x + qv.y * qv.y + qv.z * qv.z + qv.w * qv.w;
    float ks = kv.x * kv.x + kv.y * kv.y + kv.z * kv.z + kv.w * kv.w;
#pragma unroll
    for (int o = 8; o > 0; o >>= 1) {
        qs += __shfl_xor_sync(0xffffffffu, qs, o);
        ks += __shfl_xor_sync(0xffffffffu, ks, o);
    }
    const float qsc = rsqrtf(qs * (1.f / 64.f) + 1.1920929e-07f);
    const float ksc = rsqrtf(ks * (1.f / 64.f) + 1.1920929e-07f);
    float4 qn4 = make_float4(qv.x * qsc, qv.y * qsc, qv.z * qsc, qv.w * qsc);
    float4 kn4 = make_float4(kv.x * ksc, kv.y * ksc, kv.z * ksc, kv.w * ksc);
    *(float4*)&qn[tid * 4] = qn4;
    *(float4*)&kn[tid * 4] = kn4;
    __syncthreads();

    const int i = tid * 4;
    const int d = i & 63;
    const int base = i - d;
    float4 cv = *(const float4*)(cosb + t * 64 + d);
    float4 sv = *(const float4*)(sinb + t * 64 + d);
    float4 rq, rk;
    if (d < 32) {
        float4 pq = *(const float4*)&qn[base + d + 32];
        float4 pk = *(const float4*)&kn[base + d + 32];
        rq = make_float4(-pq.x, -pq.y, -pq.z, -pq.w);
        rk = make_float4(-pk.x, -pk.y, -pk.z, -pk.w);
    } else {
        rq = *(const float4*)&qn[base + d - 32];
        rk = *(const float4*)&kn[base + d - 32];
    }
    float4 oq, ok;
    oq.x = qn4.x * cv.x + rq.x * sv.x;  oq.y = qn4.y * cv.y + rq.y * sv.y;
    oq.z = qn4.z * cv.z + rq.z * sv.z;  oq.w = qn4.w * cv.w + rq.w * sv.w;
    ok.x = kn4.x * cv.x + rk.x * sv.x;  ok.y = kn4.y * cv.y + rk.y * sv.y;
    ok.z = kn4.z * cv.z + rk.z * sv.z;  ok.w = kn4.w * cv.w + rk.w * sv.w;
    *(float4*)(qrow + i) = oq;
    *(float4*)(krow + i) = ok;
}

// ---------------------------------------------------------------------------
// Flash attention v2: BQ=BKV=128, 256 threads (16x16 grid).
// S phase: 8x8 microtile (FMA-bound 64 FMA : 4 LDS).
// PV phase: 8x4 microtile, cols unrolled by 4 (128 FMA : 12 LDS).
// Q,K staged d-major (NO row swizzle — Q reads are warp-broadcast already);
// P row-major with per-row (ty&1)*4 column offset inside the padding.
// ---------------------------------------------------------------------------
#define BQ 128
#define BKV 128
#define CPAD 132
#define DPAD 68
#define ATT_SMEM ((2 * 64 * CPAD + BKV * DPAD + BQ * CPAD) * 4)

__global__ __launch_bounds__(256, 1)
void attn_kernel(const float* __restrict__ qkv, float* __restrict__ y) {
    extern __shared__ float sm[];
    float* Qs = sm;                      // [64][CPAD]  d-major
    float* Ks = Qs + 64 * CPAD;          // [64][CPAD]  d-major
    float* Vs = Ks + 64 * CPAD;          // [BKV][DPAD] natural
    float* Ps = Vs + BKV * DPAD;         // [BQ][CPAD]  row-major, col-offset per row

    const int qb = (int)(gridDim.x - 1) - (int)blockIdx.x;  // heavy CTAs first
    const int h = blockIdx.y, b = blockIdx.z;
    const int tid = threadIdx.x;
    const int ty = tid >> 4, tx = tid & 15;
    const int r0 = ty * 8;            // my 8 query rows
    const int c0 = tx * 8;            // my 8 key cols (S phase)
    const int d0 = tx * 4;            // my 4 dims (PV phase / output)
    const int psw = (ty & 1) * 4;     // P column offset (within padding, consistent R/W)

    // ---- Load Q (transposed to d-major, pre-scaled by 1/sqrt(D)) ----
    {
        const int row = tid >> 1;
        const int dh = (tid & 1) * 32;
        const float* src = qkv + ((long)(b * TT + qb * BQ + row) * 3) * 1024 + h * 64 + dh;
#pragma unroll
        for (int j = 0; j < 8; j++) {
            float4 v = *(const float4*)(src + j * 4);
            int d = dh + j * 4;
            Qs[(d + 0) * CPAD + row] = v.x * 0.125f;
            Qs[(d + 1) * CPAD + row] = v.y * 0.125f;
            Qs[(d + 2) * CPAD + row] = v.z * 0.125f;
            Qs[(d + 3) * CPAD + row] = v.w * 0.125f;
        }
    }

    float O[8][4];
    float m[8], l[8];
#pragma unroll
    for (int i = 0; i < 8; i++) {
        m[i] = -3.0e38f; l[i] = 0.f;
        O[i][0] = O[i][1] = O[i][2] = O[i][3] = 0.f;
    }

    for (int kb = 0; kb <= qb; kb++) {
        __syncthreads();  // prev PV readers done with Vs/Ps; Qs ready on iter 0
        // ---- Load K (d-major) and V (natural) ----
        {
            const int col = tid >> 1;
            const int dh = (tid & 1) * 32;
            const float* ksrc = qkv + ((long)(b * TT + kb * BKV + col) * 3 + 1) * 1024 + h * 64 + dh;
            const float* vsrc = qkv + ((long)(b * TT + kb * BKV + col) * 3 + 2) * 1024 + h * 64 + dh;
#pragma unroll
            for (int j = 0; j < 8; j++) {
                float4 v = *(const float4*)(ksrc + j * 4);
                int d = dh + j * 4;
                Ks[(d + 0) * CPAD + col] = v.x;
                Ks[(d + 1) * CPAD + col] = v.y;
                Ks[(d + 2) * CPAD + col] = v.z;
                Ks[(d + 3) * CPAD + col] = v.w;
            }
#pragma unroll
            for (int j = 0; j < 8; j++)
                *(float4*)&Vs[col * DPAD + dh + j * 4] = *(const float4*)(vsrc + j * 4);
        }
        __syncthreads();

        // ---- S = Q @ K^T (8x8 per thread) ----
        float s[8][8];
#pragma unroll
        for (int i = 0; i < 8; i++)
#pragma unroll
            for (int j = 0; j < 8; j++) s[i][j] = 0.f;

#pragma unroll 4
        for (int d = 0; d < 64; d++) {
            float4 qa  = *(const float4*)&Qs[d * CPAD + r0];
            float4 qb4 = *(const float4*)&Qs[d * CPAD + r0 + 4];
            float4 ka  = *(const float4*)&Ks[d * CPAD + c0];
            float4 kb4 = *(const float4*)&Ks[d * CPAD + c0 + 4];
            float qr[8] = {qa.x, qa.y, qa.z, qa.w, qb4.x, qb4.y, qb4.z, qb4.w};
            float kr[8] = {ka.x, ka.y, ka.z, ka.w, kb4.x, kb4.y, kb4.z, kb4.w};
#pragma unroll
            for (int i = 0; i < 8; i++)
#pragma unroll
                for (int j = 0; j < 8; j++)
                    s[i][j] += qr[i] * kr[j];
        }

        if (kb == qb) {  // causal mask on diagonal block
#pragma unroll
            for (int i = 0; i < 8; i++)
#pragma unroll
                for (int j = 0; j < 8; j++)
                    if (c0 + j > r0 + i) s[i][j] = -3.0e38f;
        }

        // ---- Online softmax (per row, reduced over 16 tx lanes) ----
#pragma unroll
        for (int i = 0; i < 8; i++) {
            float mx = s[i][0];
#pragma unroll
            for (int j = 1; j < 8; j++) mx = fmaxf(mx, s[i][j]);
            mx = fmaxf(mx, __shfl_xor_sync(0xffffffffu, mx, 1));
            mx = fmaxf(mx, __shfl_xor_sync(0xffffffffu, mx, 2));
            mx = fmaxf(mx, __shfl_xor_sync(0xffffffffu, mx, 4));
            mx = fmaxf(mx, __shfl_xor_sync(0xffffffffu, mx, 8));
            float mn = fmaxf(m[i], mx);
            float a = __expf(m[i] - mn);
            m[i] = mn;
            float ps = 0.f;
#pragma unroll
            for (int j = 0; j < 8; j++) { s[i][j] = __expf(s[i][j] - mn); ps += s[i][j]; }
            ps += __shfl_xor_sync(0xffffffffu, ps, 1);
            ps += __shfl_xor_sync(0xffffffffu, ps, 2);
            ps += __shfl_xor_sync(0xffffffffu, ps, 4);
            ps += __shfl_xor_sync(0xffffffffu, ps, 8);
            l[i] = l[i] * a + ps;
            O[i][0] *= a; O[i][1] *= a; O[i][2] *= a; O[i][3] *= a;
        }

        // ---- Write P (row-major, per-row column offset) ----
#pragma unroll
        for (int i = 0; i < 8; i++) {
            *(float4*)&Ps[(r0 + i) * CPAD + psw + c0] =
                make_float4(s[i][0], s[i][1], s[i][2], s[i][3]);
            *(float4*)&Ps[(r0 + i) * CPAD + psw + c0 + 4] =
                make_float4(s[i][4], s[i][5], s[i][6], s[i][7]);
        }
        __syncthreads();

        // ---- O += P @ V (8 rows x 4 dims per thread, cols unrolled by 4) ----
#pragma unroll 2
        for (int c = 0; c < BKV; c += 4) {
            float4 v0 = *(const float4*)&Vs[(c + 0) * DPAD + d0];
            float4 v1 = *(const float4*)&Vs[(c + 1) * DPAD + d0];
            float4 v2 = *(const float4*)&Vs[(c + 2) * DPAD + d0];
            float4 v3 = *(const float4*)&Vs[(c + 3) * DPAD + d0];
#pragma unroll
            for (int i = 0; i < 8; i++) {
                float4 p = *(const float4*)&Ps[(r0 + i) * CPAD + psw + c];
                O[i][0] += p.x * v0.x + p.y * v1.x + p.z * v2.x + p.w * v3.x;
                O[i][1] += p.x * v0.y + p.y * v1.y + p.z * v2.y + p.w * v3.y;
                O[i][2] += p.x * v0.z + p.y * v1.z + p.z * v2.z + p.w * v3.z;
                O[i][3] += p.x * v0.w + p.y * v1.w + p.z * v2.w + p.w * v3.w;
            }
        }
    }

    // ---- Epilogue ----
#pragma unroll
    for (int i = 0; i < 8; i++) {
        float inv = 1.0f / l[i];
        float* dst = y + (long)(b * TT + qb * BQ + r0 + i) * 1024 + h * 64 + d0;
        *(float4*)dst = make_float4(O[i][0] * inv, O[i][1] * inv,
                                    O[i][2] * inv, O[i][3] * inv);
    }
}

// ---------------------------------------------------------------------------
extern "C" void kernel_launch(void* const* d_in, const int* in_sizes, int n_in,
                              void* d_out, int out_size) {
    const float* x      = (const float*)d_in[0];
    const float* cosb   = (const float*)d_in[1];
    const float* sinb   = (const float*)d_in[2];
    const float* W_attn = (const float*)d_in[3];
    const float* b_attn = (const float*)d_in[4];
    const float* W_proj = (const float*)d_in[5];
    const float* b_proj = (const float*)d_in[6];
    float* out = (float*)d_out;

    float *qkv, *y;
    cudaGetSymbolAddress((void**)&qkv, g_qkv);
    cudaGetSymbolAddress((void**)&y, g_y);

    // 1) QKV GEMM: [4096,1024] @ [1024,3072] + bias
    sgemm_bias_kernel<<<dim3(3072 / BN, 4096 / BM), 256>>>(x, W_attn, b_attn, qkv, 4096, 3072, 1024);

    // 2) per-head RMSNorm + RoPE on q,k (in place)
    norm_rope_kernel<<<2 * TT, 256>>>(qkv, cosb, sinb);

    // 3) causal flash attention
    cudaFuncSetAttribute(attn_kernel, cudaFuncAttributeMaxDynamicSharedMemorySize, ATT_SMEM);
    attn_kernel<<<dim3(TT / BQ, 16, 2), 256, ATT_SMEM>>>(qkv, y);

    // 4) output projection: [4096,1024] @ [1024,1024] + bias
    sgemm_bias_kernel<<<dim3(1024 / BN, 4096 / BM), 256>>>(y, W_proj, b_proj, out, 4096, 1024, 1024);
}

// round 4
// speedup vs baseline: 3.7654x; 1.5709x over previous
#include <cuda_runtime.h>
#include <cstdint>

// Problem constants: B=2, T=2048, C=1024, H=16, D=64
#define TT 2048

// Scratch (allocation-free rule: __device__ globals)
__device__ float g_qkv[2 * 2048 * 3 * 1024];  // [B,T,3,H,D]
__device__ float g_y[2 * 2048 * 1024];        // [B,T,H,D]

// ---------------------------------------------------------------------------
// TF32 tensor-core GEMM with bias: C[M,N] = A[M,K] @ B[K,N] + bias[N]
// 128x128 CTA tile, BK=16, 8 warps (4x2), warp tile 32x64 = 2x8 m16n8k8.
// ---------------------------------------------------------------------------
#define PADK 20    // As row stride: gid*20 mod 32 -> {0,20,8,28,16,4,24,12} conflict-free
#define PADN 136   // Bs row stride: tig*136 mod 32 -> {0,8,16,24} conflict-free with gid

__device__ __forceinline__ uint32_t f2tf32(float f) {
    uint32_t r;
    asm("cvt.rna.tf32.f32 %0, %1;" : "=r"(r) : "f"(f));
    return r;
}

__device__ __forceinline__ void mma_tf32(float* c, const uint32_t* a, const uint32_t* b) {
    asm volatile(
        "mma.sync.aligned.m16n8k8.row.col.f32.tf32.tf32.f32 "
        "{%0,%1,%2,%3}, {%4,%5,%6,%7}, {%8,%9}, {%0,%1,%2,%3};\n"
        : "+f"(c[0]), "+f"(c[1]), "+f"(c[2]), "+f"(c[3])
        : "r"(a[0]), "r"(a[1]), "r"(a[2]), "r"(a[3]), "r"(b[0]), "r"(b[1]));
}

__global__ __launch_bounds__(256, 2)
void tf32_gemm_bias(const float* __restrict__ A, const float* __restrict__ Bw,
                    const float* __restrict__ bias, float* __restrict__ Cout,
                    int M, int N, int K) {
    __shared__ uint32_t As[128 * PADK];
    __shared__ uint32_t Bs[16 * PADN];

    const int tid = threadIdx.x;
    const int lane = tid & 31;
    const int warp = tid >> 5;
    const int gid = lane >> 2;   // 0..7
    const int tig = lane & 3;    // 0..3
    const int wm = warp >> 1;    // 0..3
    const int wn = warp & 1;     // 0..1
    const int m0w = wm * 32;
    const int n0w = wn * 64;
    const int br = blockIdx.y * 128;
    const int bc = blockIdx.x * 128;

    // Global load mapping
    const int arow = tid >> 2;             // 0..63 (second chunk +64)
    const int akc  = (tid & 3) * 4;
    const int bkr  = tid >> 5;             // 0..7 (second chunk +8)
    const int bnc  = (tid & 31) * 4;

    const float* Ap0 = A + (long)(br + arow) * K + akc;
    const float* Ap1 = A + (long)(br + arow + 64) * K + akc;
    const float* Bp0 = Bw + (long)bkr * N + bc + bnc;
    const float* Bp1 = Bw + (long)(bkr + 8) * N + bc + bnc;

    float c[2][8][4];
#pragma unroll
    for (int mi = 0; mi < 2; mi++)
#pragma unroll
        for (int nj = 0; nj < 8; nj++)
#pragma unroll
            for (int e = 0; e < 4; e++) c[mi][nj][e] = 0.f;

    // Prefetch first tile
    float4 ag0 = *(const float4*)(Ap0);
    float4 ag1 = *(const float4*)(Ap1);
    float4 bg0 = *(const float4*)(Bp0);
    float4 bg1 = *(const float4*)(Bp1);

    for (int k0 = 0; k0 < K; k0 += 16) {
        // Store current tile to smem (convert to tf32)
        {
            uint4 s;
            s.x = f2tf32(ag0.x); s.y = f2tf32(ag0.y); s.z = f2tf32(ag0.z); s.w = f2tf32(ag0.w);
            *(uint4*)&As[arow * PADK + akc] = s;
            s.x = f2tf32(ag1.x); s.y = f2tf32(ag1.y); s.z = f2tf32(ag1.z); s.w = f2tf32(ag1.w);
            *(uint4*)&As[(arow + 64) * PADK + akc] = s;
            s.x = f2tf32(bg0.x); s.y = f2tf32(bg0.y); s.z = f2tf32(bg0.z); s.w = f2tf32(bg0.w);
            *(uint4*)&Bs[bkr * PADN + bnc] = s;
            s.x = f2tf32(bg1.x); s.y = f2tf32(bg1.y); s.z = f2tf32(bg1.z); s.w = f2tf32(bg1.w);
            *(uint4*)&Bs[(bkr + 8) * PADN + bnc] = s;
        }
        __syncthreads();

        // Prefetch next tile (overlaps with the math below)
        if (k0 + 16 < K) {
            ag0 = *(const float4*)(Ap0 + k0 + 16);
            ag1 = *(const float4*)(Ap1 + k0 + 16);
            bg0 = *(const float4*)(Bp0 + (long)(k0 + 16) * N);
            bg1 = *(const float4*)(Bp1 + (long)(k0 + 16) * N);
        }

        // Math: two k-steps of 8
#pragma unroll
        for (int ks = 0; ks < 16; ks += 8) {
            uint32_t a[2][4];
#pragma unroll
            for (int mi = 0; mi < 2; mi++) {
                int base = (m0w + mi * 16 + gid) * PADK + ks + tig;
                a[mi][0] = As[base];
                a[mi][1] = As[base + 8 * PADK];
                a[mi][2] = As[base + 4];
                a[mi][3] = As[base + 8 * PADK + 4];
            }
            uint32_t b[8][2];
#pragma unroll
            for (int nj = 0; nj < 8; nj++) {
                int base = (ks + tig) * PADN + n0w + nj * 8 + gid;
                b[nj][0] = Bs[base];
                b[nj][1] = Bs[base + 4 * PADN];
            }
#pragma unroll
            for (int mi = 0; mi < 2; mi++)
#pragma unroll
                for (int nj = 0; nj < 8; nj++)
                    mma_tf32(c[mi][nj], a[mi], b[nj]);
        }
        __syncthreads();
    }

    // Epilogue: add bias, store float2 pairs
#pragma unroll
    for (int mi = 0; mi < 2; mi++) {
        int row = br + m0w + mi * 16 + gid;
#pragma unroll
        for (int nj = 0; nj < 8; nj++) {
            int col = bc + n0w + nj * 8 + tig * 2;
            float2 bb = *(const float2*)(bias + col);
            float2 o0 = make_float2(c[mi][nj][0] + bb.x, c[mi][nj][1] + bb.y);
            float2 o1 = make_float2(c[mi][nj][2] + bb.x, c[mi][nj][3] + bb.y);
            *(float2*)(Cout + (long)row * N + col) = o0;
            *(float2*)(Cout + (long)(row + 8) * N + col) = o1;
        }
    }
}

// ---------------------------------------------------------------------------
// Fused per-head RMSNorm + RoPE on q and k slots of g_qkv (in place).
// ---------------------------------------------------------------------------
__global__ __launch_bounds__(256)
void norm_rope_kernel(float* __restrict__ qkv,
                      const float* __restrict__ cosb,
                      const float* __restrict__ sinb) {
    __shared__ float qn[1024];
    __shared__ float kn[1024];
    const int bt = blockIdx.x;
    const int t = bt & (TT - 1);
    const int tid = threadIdx.x;
    float* qrow = qkv + (long)bt * 3072;
    float* krow = qrow + 1024;

    float4 qv = *(const float4*)(qrow + tid * 4);
    float4 kv = *(const float4*)(krow + tid * 4);
    float qs = qv.x * qv.x + qv.y * qv.y + qv.z * qv.z + qv.w * qv.w;
    float ks = kv.x * kv.x + kv.y * kv.y + kv.z * kv.z + kv.w * kv.w;
#pragma unroll
    for (int o = 8; o > 0; o >>= 1) {
        qs += __shfl_xor_sync(0xffffffffu, qs, o);
        ks += __shfl_xor_sync(0xffffffffu, ks, o);
    }
    const float qsc = rsqrtf(qs * (1.f / 64.f) + 1.1920929e-07f);
    const float ksc = rsqrtf(ks * (1.f / 64.f) + 1.1920929e-07f);
    float4 qn4 = make_float4(qv.x * qsc, qv.y * qsc, qv.z * qsc, qv.w * qsc);
    float4 kn4 = make_float4(kv.x * ksc, kv.y * ksc, kv.z * ksc, kv.w * ksc);
    *(float4*)&qn[tid * 4] = qn4;
    *(float4*)&kn[tid * 4] = kn4;
    __syncthreads();

    const int i = tid * 4;
    const int d = i & 63;
    const int base = i - d;
    float4 cv = *(const float4*)(cosb + t * 64 + d);
    float4 sv = *(const float4*)(sinb + t * 64 + d);
    float4 rq, rk;
    if (d < 32) {
        float4 pq = *(const float4*)&qn[base + d + 32];
        float4 pk = *(const float4*)&kn[base + d + 32];
        rq = make_float4(-pq.x, -pq.y, -pq.z, -pq.w);
        rk = make_float4(-pk.x, -pk.y, -pk.z, -pk.w);
    } else {
        rq = *(const float4*)&qn[base + d - 32];
        rk = *(const float4*)&kn[base + d - 32];
    }
    float4 oq, ok;
    oq.x = qn4.x * cv.x + rq.x * sv.x;  oq.y = qn4.y * cv.y + rq.y * sv.y;
    oq.z = qn4.z * cv.z + rq.z * sv.z;  oq.w = qn4.w * cv.w + rq.w * sv.w;
    ok.x = kn4.x * cv.x + rk.x * sv.x;  ok.y = kn4.y * cv.y + rk.y * sv.y;
    ok.z = kn4.z * cv.z + rk.z * sv.z;  ok.w = kn4.w * cv.w + rk.w * sv.w;
    *(float4*)(qrow + i) = oq;
    *(float4*)(krow + i) = ok;
}

// ---------------------------------------------------------------------------
// Flash attention v2: BQ=BKV=128, 256 threads (16x16 grid). fp32 FFMA.
// ---------------------------------------------------------------------------
#define BQ 128
#define BKV 128
#define CPAD 132
#define DPAD 68
#define ATT_SMEM ((2 * 64 * CPAD + BKV * DPAD + BQ * CPAD) * 4)

__global__ __launch_bounds__(256, 1)
void attn_kernel(const float* __restrict__ qkv, float* __restrict__ y) {
    extern __shared__ float sm[];
    float* Qs = sm;                      // [64][CPAD]  d-major
    float* Ks = Qs + 64 * CPAD;          // [64][CPAD]  d-major
    float* Vs = Ks + 64 * CPAD;          // [BKV][DPAD] natural
    float* Ps = Vs + BKV * DPAD;         // [BQ][CPAD]  row-major, col-offset per row

    const int qb = (int)(gridDim.x - 1) - (int)blockIdx.x;  // heavy CTAs first
    const int h = blockIdx.y, b = blockIdx.z;
    const int tid = threadIdx.x;
    const int ty = tid >> 4, tx = tid & 15;
    const int r0 = ty * 8;
    const int c0 = tx * 8;
    const int d0 = tx * 4;
    const int psw = (ty & 1) * 4;

    {
        const int row = tid >> 1;
        const int dh = (tid & 1) * 32;
        const float* src = qkv + ((long)(b * TT + qb * BQ + row) * 3) * 1024 + h * 64 + dh;
#pragma unroll
        for (int j = 0; j < 8; j++) {
            float4 v = *(const float4*)(src + j * 4);
            int d = dh + j * 4;
            Qs[(d + 0) * CPAD + row] = v.x * 0.125f;
            Qs[(d + 1) * CPAD + row] = v.y * 0.125f;
            Qs[(d + 2) * CPAD + row] = v.z * 0.125f;
            Qs[(d + 3) * CPAD + row] = v.w * 0.125f;
        }
    }

    float O[8][4];
    float m[8], l[8];
#pragma unroll
    for (int i = 0; i < 8; i++) {
        m[i] = -3.0e38f; l[i] = 0.f;
        O[i][0] = O[i][1] = O[i][2] = O[i][3] = 0.f;
    }

    for (int kb = 0; kb <= qb; kb++) {
        __syncthreads();
        {
            const int col = tid >> 1;
            const int dh = (tid & 1) * 32;
            const float* ksrc = qkv + ((long)(b * TT + kb * BKV + col) * 3 + 1) * 1024 + h * 64 + dh;
            const float* vsrc = qkv + ((long)(b * TT + kb * BKV + col) * 3 + 2) * 1024 + h * 64 + dh;
#pragma unroll
            for (int j = 0; j < 8; j++) {
                float4 v = *(const float4*)(ksrc + j * 4);
                int d = dh + j * 4;
                Ks[(d + 0) * CPAD + col] = v.x;
                Ks[(d + 1) * CPAD + col] = v.y;
                Ks[(d + 2) * CPAD + col] = v.z;
                Ks[(d + 3) * CPAD + col] = v.w;
            }
#pragma unroll
            for (int j = 0; j < 8; j++)
                *(float4*)&Vs[col * DPAD + dh + j * 4] = *(const float4*)(vsrc + j * 4);
        }
        __syncthreads();

        float s[8][8];
#pragma unroll
        for (int i = 0; i < 8; i++)
#pragma unroll
            for (int j = 0; j < 8; j++) s[i][j] = 0.f;

#pragma unroll 4
        for (int d = 0; d < 64; d++) {
            float4 qa  = *(const float4*)&Qs[d * CPAD + r0];
            float4 qb4 = *(const float4*)&Qs[d * CPAD + r0 + 4];
            float4 ka  = *(const float4*)&Ks[d * CPAD + c0];
            float4 kb4 = *(const float4*)&Ks[d * CPAD + c0 + 4];
            float qr[8] = {qa.x, qa.y, qa.z, qa.w, qb4.x, qb4.y, qb4.z, qb4.w};
            float kr[8] = {ka.x, ka.y, ka.z, ka.w, kb4.x, kb4.y, kb4.z, kb4.w};
#pragma unroll
            for (int i = 0; i < 8; i++)
#pragma unroll
                for (int j = 0; j < 8; j++)
                    s[i][j] += qr[i] * kr[j];
        }

        if (kb == qb) {
#pragma unroll
            for (int i = 0; i < 8; i++)
#pragma unroll
                for (int j = 0; j < 8; j++)
                    if (c0 + j > r0 + i) s[i][j] = -3.0e38f;
        }

#pragma unroll
        for (int i = 0; i < 8; i++) {
            float mx = s[i][0];
#pragma unroll
            for (int j = 1; j < 8; j++) mx = fmaxf(mx, s[i][j]);
            mx = fmaxf(mx, __shfl_xor_sync(0xffffffffu, mx, 1));
            mx = fmaxf(mx, __shfl_xor_sync(0xffffffffu, mx, 2));
            mx = fmaxf(mx, __shfl_xor_sync(0xffffffffu, mx, 4));
            mx = fmaxf(mx, __shfl_xor_sync(0xffffffffu, mx, 8));
            float mn = fmaxf(m[i], mx);
            float a = __expf(m[i] - mn);
            m[i] = mn;
            float ps = 0.f;
#pragma unroll
            for (int j = 0; j < 8; j++) { s[i][j] = __expf(s[i][j] - mn); ps += s[i][j]; }
            ps += __shfl_xor_sync(0xffffffffu, ps, 1);
            ps += __shfl_xor_sync(0xffffffffu, ps, 2);
            ps += __shfl_xor_sync(0xffffffffu, ps, 4);
            ps += __shfl_xor_sync(0xffffffffu, ps, 8);
            l[i] = l[i] * a + ps;
            O[i][0] *= a; O[i][1] *= a; O[i][2] *= a; O[i][3] *= a;
        }

#pragma unroll
        for (int i = 0; i < 8; i++) {
            *(float4*)&Ps[(r0 + i) * CPAD + psw + c0] =
                make_float4(s[i][0], s[i][1], s[i][2], s[i][3]);
            *(float4*)&Ps[(r0 + i) * CPAD + psw + c0 + 4] =
                make_float4(s[i][4], s[i][5], s[i][6], s[i][7]);
        }
        __syncthreads();

#pragma unroll 2
        for (int c = 0; c < BKV; c += 4) {
            float4 v0 = *(const float4*)&Vs[(c + 0) * DPAD + d0];
            float4 v1 = *(const float4*)&Vs[(c + 1) * DPAD + d0];
            float4 v2 = *(const float4*)&Vs[(c + 2) * DPAD + d0];
            float4 v3 = *(const float4*)&Vs[(c + 3) * DPAD + d0];
#pragma unroll
            for (int i = 0; i < 8; i++) {
                float4 p = *(const float4*)&Ps[(r0 + i) * CPAD + psw + c];
                O[i][0] += p.x * v0.x + p.y * v1.x + p.z * v2.x + p.w * v3.x;
                O[i][1] += p.x * v0.y + p.y * v1.y + p.z * v2.y + p.w * v3.y;
                O[i][2] += p.x * v0.z + p.y * v1.z + p.z * v2.z + p.w * v3.z;
                O[i][3] += p.x * v0.w + p.y * v1.w + p.z * v2.w + p.w * v3.w;
            }
        }
    }

#pragma unroll
    for (int i = 0; i < 8; i++) {
        float inv = 1.0f / l[i];
        float* dst = y + (long)(b * TT + qb * BQ + r0 + i) * 1024 + h * 64 + d0;
        *(float4*)dst = make_float4(O[i][0] * inv, O[i][1] * inv,
                                    O[i][2] * inv, O[i][3] * inv);
    }
}

// ---------------------------------------------------------------------------
extern "C" void kernel_launch(void* const* d_in, const int* in_sizes, int n_in,
                              void* d_out, int out_size) {
    const float* x      = (const float*)d_in[0];
    const float* cosb   = (const float*)d_in[1];
    const float* sinb   = (const float*)d_in[2];
    const float* W_attn = (const float*)d_in[3];
    const float* b_attn = (const float*)d_in[4];
    const float* W_proj = (const float*)d_in[5];
    const float* b_proj = (const float*)d_in[6];
    float* out = (float*)d_out;

    float *qkv, *y;
    cudaGetSymbolAddress((void**)&qkv, g_qkv);
    cudaGetSymbolAddress((void**)&y, g_y);

    // 1) QKV GEMM (TF32 tensor cores): [4096,1024] @ [1024,3072] + bias
    tf32_gemm_bias<<<dim3(3072 / 128, 4096 / 128), 256>>>(x, W_attn, b_attn, qkv, 4096, 3072, 1024);

    // 2) per-head RMSNorm + RoPE on q,k (in place)
    norm_rope_kernel<<<2 * TT, 256>>>(qkv, cosb, sinb);

    // 3) causal flash attention (fp32)
    cudaFuncSetAttribute(attn_kernel, cudaFuncAttributeMaxDynamicSharedMemorySize, ATT_SMEM);
    attn_kernel<<<dim3(TT / BQ, 16, 2), 256, ATT_SMEM>>>(qkv, y);

    // 4) output projection (TF32 tensor cores): [4096,1024] @ [1024,1024] + bias
    tf32_gemm_bias<<<dim3(1024 / 128, 4096 / 128), 256>>>(y, W_proj, b_proj, out, 4096, 1024, 1024);
}

// round 5
// speedup vs baseline: 5.9329x; 1.5756x over previous
#include <cuda_runtime.h>
#include <cstdint>

// Problem constants: B=2, T=2048, C=1024, H=16, D=64
#define TT 2048

// Scratch (allocation-free rule: __device__ globals)
__device__ float g_qkv[2 * 2048 * 3 * 1024];  // [B,T,3,H,D]
__device__ float g_y[2 * 2048 * 1024];        // [B,T,H,D]

__device__ __forceinline__ uint32_t f2tf32(float f) {
    uint32_t r;
    asm("cvt.rna.tf32.f32 %0, %1;" : "=r"(r) : "f"(f));
    return r;
}

__device__ __forceinline__ void mma_tf32(float* c, const uint32_t* a, const uint32_t* b) {
    asm volatile(
        "mma.sync.aligned.m16n8k8.row.col.f32.tf32.tf32.f32 "
        "{%0,%1,%2,%3}, {%4,%5,%6,%7}, {%8,%9}, {%0,%1,%2,%3};\n"
        : "+f"(c[0]), "+f"(c[1]), "+f"(c[2]), "+f"(c[3])
        : "r"(a[0]), "r"(a[1]), "r"(a[2]), "r"(a[3]), "r"(b[0]), "r"(b[1]));
}

// ---------------------------------------------------------------------------
// TF32 tensor-core GEMM with bias: C[M,N] = A[M,K] @ B[K,N] + bias[N]
// 128x128 CTA tile, BK=16, 8 warps (4x2), warp tile 32x64 = 2x8 m16n8k8.
// ---------------------------------------------------------------------------
#define PADK 20
#define PADN 136

__global__ __launch_bounds__(256, 2)
void tf32_gemm_bias(const float* __restrict__ A, const float* __restrict__ Bw,
                    const float* __restrict__ bias, float* __restrict__ Cout,
                    int M, int N, int K) {
    __shared__ uint32_t As[128 * PADK];
    __shared__ uint32_t Bs[16 * PADN];

    const int tid = threadIdx.x;
    const int lane = tid & 31;
    const int warp = tid >> 5;
    const int gid = lane >> 2;
    const int tig = lane & 3;
    const int wm = warp >> 1;
    const int wn = warp & 1;
    const int m0w = wm * 32;
    const int n0w = wn * 64;
    const int br = blockIdx.y * 128;
    const int bc = blockIdx.x * 128;

    const int arow = tid >> 2;
    const int akc  = (tid & 3) * 4;
    const int bkr  = tid >> 5;
    const int bnc  = (tid & 31) * 4;

    const float* Ap0 = A + (long)(br + arow) * K + akc;
    const float* Ap1 = A + (long)(br + arow + 64) * K + akc;
    const float* Bp0 = Bw + (long)bkr * N + bc + bnc;
    const float* Bp1 = Bw + (long)(bkr + 8) * N + bc + bnc;

    float c[2][8][4];
#pragma unroll
    for (int mi = 0; mi < 2; mi++)
#pragma unroll
        for (int nj = 0; nj < 8; nj++)
#pragma unroll
            for (int e = 0; e < 4; e++) c[mi][nj][e] = 0.f;

    float4 ag0 = *(const float4*)(Ap0);
    float4 ag1 = *(const float4*)(Ap1);
    float4 bg0 = *(const float4*)(Bp0);
    float4 bg1 = *(const float4*)(Bp1);

    for (int k0 = 0; k0 < K; k0 += 16) {
        {
            uint4 s;
            s.x = f2tf32(ag0.x); s.y = f2tf32(ag0.y); s.z = f2tf32(ag0.z); s.w = f2tf32(ag0.w);
            *(uint4*)&As[arow * PADK + akc] = s;
            s.x = f2tf32(ag1.x); s.y = f2tf32(ag1.y); s.z = f2tf32(ag1.z); s.w = f2tf32(ag1.w);
            *(uint4*)&As[(arow + 64) * PADK + akc] = s;
            s.x = f2tf32(bg0.x); s.y = f2tf32(bg0.y); s.z = f2tf32(bg0.z); s.w = f2tf32(bg0.w);
            *(uint4*)&Bs[bkr * PADN + bnc] = s;
            s.x = f2tf32(bg1.x); s.y = f2tf32(bg1.y); s.z = f2tf32(bg1.z); s.w = f2tf32(bg1.w);
            *(uint4*)&Bs[(bkr + 8) * PADN + bnc] = s;
        }
        __syncthreads();

        if (k0 + 16 < K) {
            ag0 = *(const float4*)(Ap0 + k0 + 16);
            ag1 = *(const float4*)(Ap1 + k0 + 16);
            bg0 = *(const float4*)(Bp0 + (long)(k0 + 16) * N);
            bg1 = *(const float4*)(Bp1 + (long)(k0 + 16) * N);
        }

#pragma unroll
        for (int ks = 0; ks < 16; ks += 8) {
            uint32_t a[2][4];
#pragma unroll
            for (int mi = 0; mi < 2; mi++) {
                int base = (m0w + mi * 16 + gid) * PADK + ks + tig;
                a[mi][0] = As[base];
                a[mi][1] = As[base + 8 * PADK];
                a[mi][2] = As[base + 4];
                a[mi][3] = As[base + 8 * PADK + 4];
            }
            uint32_t b[8][2];
#pragma unroll
            for (int nj = 0; nj < 8; nj++) {
                int base = (ks + tig) * PADN + n0w + nj * 8 + gid;
                b[nj][0] = Bs[base];
                b[nj][1] = Bs[base + 4 * PADN];
            }
#pragma unroll
            for (int mi = 0; mi < 2; mi++)
#pragma unroll
                for (int nj = 0; nj < 8; nj++)
                    mma_tf32(c[mi][nj], a[mi], b[nj]);
        }
        __syncthreads();
    }

#pragma unroll
    for (int mi = 0; mi < 2; mi++) {
        int row = br + m0w + mi * 16 + gid;
#pragma unroll
        for (int nj = 0; nj < 8; nj++) {
            int col = bc + n0w + nj * 8 + tig * 2;
            float2 bb = *(const float2*)(bias + col);
            float2 o0 = make_float2(c[mi][nj][0] + bb.x, c[mi][nj][1] + bb.y);
            float2 o1 = make_float2(c[mi][nj][2] + bb.x, c[mi][nj][3] + bb.y);
            *(float2*)(Cout + (long)row * N + col) = o0;
            *(float2*)(Cout + (long)(row + 8) * N + col) = o1;
        }
    }
}

// ---------------------------------------------------------------------------
// Fused per-head RMSNorm + RoPE on q and k slots of g_qkv (in place).
// ---------------------------------------------------------------------------
__global__ __launch_bounds__(256)
void norm_rope_kernel(float* __restrict__ qkv,
                      const float* __restrict__ cosb,
                      const float* __restrict__ sinb) {
    __shared__ float qn[1024];
    __shared__ float kn[1024];
    const int bt = blockIdx.x;
    const int t = bt & (TT - 1);
    const int tid = threadIdx.x;
    float* qrow = qkv + (long)bt * 3072;
    float* krow = qrow + 1024;

    float4 qv = *(const float4*)(qrow + tid * 4);
    float4 kv = *(const float4*)(krow + tid * 4);
    float qs = qv.x * qv.x + qv.y * qv.y + qv.z * qv.z + qv.w * qv.w;
    float ks = kv.x * kv.x + kv.y * kv.y + kv.z * kv.z + kv.w * kv.w;
#pragma unroll
    for (int o = 8; o > 0; o >>= 1) {
        qs += __shfl_xor_sync(0xffffffffu, qs, o);
        ks += __shfl_xor_sync(0xffffffffu, ks, o);
    }
    const float qsc = rsqrtf(qs * (1.f / 64.f) + 1.1920929e-07f);
    const float ksc = rsqrtf(ks * (1.f / 64.f) + 1.1920929e-07f);
    float4 qn4 = make_float4(qv.x * qsc, qv.y * qsc, qv.z * qsc, qv.w * qsc);
    float4 kn4 = make_float4(kv.x * ksc, kv.y * ksc, kv.z * ksc, kv.w * ksc);
    *(float4*)&qn[tid * 4] = qn4;
    *(float4*)&kn[tid * 4] = kn4;
    __syncthreads();

    const int i = tid * 4;
    const int d = i & 63;
    const int base = i - d;
    float4 cv = *(const float4*)(cosb + t * 64 + d);
    float4 sv = *(const float4*)(sinb + t * 64 + d);
    float4 rq, rk;
    if (d < 32) {
        float4 pq = *(const float4*)&qn[base + d + 32];
        float4 pk = *(const float4*)&kn[base + d + 32];
        rq = make_float4(-pq.x, -pq.y, -pq.z, -pq.w);
        rk = make_float4(-pk.x, -pk.y, -pk.z, -pk.w);
    } else {
        rq = *(const float4*)&qn[base + d - 32];
        rk = *(const float4*)&kn[base + d - 32];
    }
    float4 oq, ok;
    oq.x = qn4.x * cv.x + rq.x * sv.x;  oq.y = qn4.y * cv.y + rq.y * sv.y;
    oq.z = qn4.z * cv.z + rq.z * sv.z;  oq.w = qn4.w * cv.w + rq.w * sv.w;
    ok.x = kn4.x * cv.x + rk.x * sv.x;  ok.y = kn4.y * cv.y + rk.y * sv.y;
    ok.z = kn4.z * cv.z + rk.z * sv.z;  ok.w = kn4.w * cv.w + rk.w * sv.w;
    *(float4*)(qrow + i) = oq;
    *(float4*)(krow + i) = ok;
}

// ---------------------------------------------------------------------------
// TF32 flash attention: BQ=BKV=128, 8 warps, warp = 16 rows x 128 kv cols.
// Q fragments in registers (loaded once). K natural [kv][KPAD], V [kv][VPAD],
// P round-trip via smem [128][PPAD]. Pads chosen for conflict-free frag LDS.
// ---------------------------------------------------------------------------
#define KPAD 68    // frag lanes: 4*gid + tig -> all 32 banks
#define VPAD 72    // frag lanes: 8*tig + gid -> all 32 banks
#define PPAD 132   // frag lanes: 4*gid + tig -> all 32 banks
#define ATT_SMEM ((128 * KPAD + 128 * VPAD + 128 * PPAD) * 4)

__global__ __launch_bounds__(256, 1)
void attn_tf32_kernel(const float* __restrict__ qkv, float* __restrict__ y) {
    extern __shared__ uint32_t smu[];
    uint32_t* Ks = smu;                 // [128][KPAD]
    uint32_t* Vs = Ks + 128 * KPAD;     // [128][VPAD]
    uint32_t* Ps = Vs + 128 * VPAD;     // [128][PPAD] (aliased as Q staging [128][KPAD])

    const int qb = (int)(gridDim.x - 1) - (int)blockIdx.x;  // heavy CTAs first
    const int h = blockIdx.y, b = blockIdx.z;
    const int tid = threadIdx.x;
    const int lane = tid & 31, warp = tid >> 5;
    const int gid = lane >> 2, tig = lane & 3;
    const int r0 = warp * 16;  // warp's 16 rows within the 128-row tile

    // ---- Stage Q (scaled, tf32) into Ps-alias, then load A-fragments ----
    {
        const int row = tid >> 1;
        const int dh = (tid & 1) * 32;
        const float* src = qkv + ((long)(b * TT + qb * 128 + row) * 3) * 1024 + h * 64 + dh;
#pragma unroll
        for (int j = 0; j < 8; j++) {
            float4 v = *(const float4*)(src + j * 4);
            uint4 s;
            s.x = f2tf32(v.x * 0.125f); s.y = f2tf32(v.y * 0.125f);
            s.z = f2tf32(v.z * 0.125f); s.w = f2tf32(v.w * 0.125f);
            *(uint4*)&Ps[row * KPAD + dh + j * 4] = s;
        }
    }
    __syncthreads();
    uint32_t qa[8][4];
#pragma unroll
    for (int ks = 0; ks < 8; ks++) {
        int base = (r0 + gid) * KPAD + ks * 8 + tig;
        qa[ks][0] = Ps[base];
        qa[ks][1] = Ps[base + 8 * KPAD];
        qa[ks][2] = Ps[base + 4];
        qa[ks][3] = Ps[base + 8 * KPAD + 4];
    }

    float cO[8][4];
#pragma unroll
    for (int nj = 0; nj < 8; nj++)
#pragma unroll
        for (int e = 0; e < 4; e++) cO[nj][e] = 0.f;
    float mrow0 = -3.0e38f, mrow1 = -3.0e38f, lrow0 = 0.f, lrow1 = 0.f;

    for (int kb = 0; kb <= qb; kb++) {
        __syncthreads();  // prev iter PV done reading Vs/Ps; all warps past Q-frag loads
        // ---- Load K, V tiles (tf32) ----
        {
            const int row = tid >> 1;
            const int dh = (tid & 1) * 32;
            const float* ksrc = qkv + ((long)(b * TT + kb * 128 + row) * 3 + 1) * 1024 + h * 64 + dh;
            const float* vsrc = qkv + ((long)(b * TT + kb * 128 + row) * 3 + 2) * 1024 + h * 64 + dh;
#pragma unroll
            for (int j = 0; j < 8; j++) {
                float4 v = *(const float4*)(ksrc + j * 4);
                uint4 s;
                s.x = f2tf32(v.x); s.y = f2tf32(v.y); s.z = f2tf32(v.z); s.w = f2tf32(v.w);
                *(uint4*)&Ks[row * KPAD + dh + j * 4] = s;
                v = *(const float4*)(vsrc + j * 4);
                s.x = f2tf32(v.x); s.y = f2tf32(v.y); s.z = f2tf32(v.z); s.w = f2tf32(v.w);
                *(uint4*)&Vs[row * VPAD + dh + j * 4] = s;
            }
        }
        __syncthreads();

        // ---- S = Q @ K^T : warp computes 16 rows x 128 cols (16 n-tiles) ----
        float cS[16][4];
#pragma unroll
        for (int nj = 0; nj < 16; nj++)
#pragma unroll
            for (int e = 0; e < 4; e++) cS[nj][e] = 0.f;

#pragma unroll
        for (int ks = 0; ks < 8; ks++) {
#pragma unroll
            for (int nj = 0; nj < 16; nj++) {
                uint32_t bb[2];
                int base = (nj * 8 + gid) * KPAD + ks * 8 + tig;
                bb[0] = Ks[base];
                bb[1] = Ks[base + 4];
                mma_tf32(cS[nj], qa[ks], bb);
            }
        }

        if (kb == qb) {  // causal mask on diagonal block (block-local coords)
            int rA = r0 + gid, rB = rA + 8;
#pragma unroll
            for (int nj = 0; nj < 16; nj++) {
                int col = nj * 8 + 2 * tig;
                if (col     > rA) cS[nj][0] = -3.0e38f;
                if (col + 1 > rA) cS[nj][1] = -3.0e38f;
                if (col     > rB) cS[nj][2] = -3.0e38f;
                if (col + 1 > rB) cS[nj][3] = -3.0e38f;
            }
        }

        // ---- Online softmax (2 rows per thread; reduce over 4 tig lanes) ----
        float mx0 = -3.0e38f, mx1 = -3.0e38f;
#pragma unroll
        for (int nj = 0; nj < 16; nj++) {
            mx0 = fmaxf(mx0, fmaxf(cS[nj][0], cS[nj][1]));
            mx1 = fmaxf(mx1, fmaxf(cS[nj][2], cS[nj][3]));
        }
        mx0 = fmaxf(mx0, __shfl_xor_sync(0xffffffffu, mx0, 1));
        mx0 = fmaxf(mx0, __shfl_xor_sync(0xffffffffu, mx0, 2));
        mx1 = fmaxf(mx1, __shfl_xor_sync(0xffffffffu, mx1, 1));
        mx1 = fmaxf(mx1, __shfl_xor_sync(0xffffffffu, mx1, 2));
        float mn0 = fmaxf(mrow0, mx0), mn1 = fmaxf(mrow1, mx1);
        float a0 = __expf(mrow0 - mn0), a1 = __expf(mrow1 - mn1);
        mrow0 = mn0; mrow1 = mn1;
        float s0 = 0.f, s1 = 0.f;
#pragma unroll
        for (int nj = 0; nj < 16; nj++) {
            cS[nj][0] = __expf(cS[nj][0] - mn0); s0 += cS[nj][0];
            cS[nj][1] = __expf(cS[nj][1] - mn0); s0 += cS[nj][1];
            cS[nj][2] = __expf(cS[nj][2] - mn1); s1 += cS[nj][2];
            cS[nj][3] = __expf(cS[nj][3] - mn1); s1 += cS[nj][3];
        }
        s0 += __shfl_xor_sync(0xffffffffu, s0, 1);
        s0 += __shfl_xor_sync(0xffffffffu, s0, 2);
        s1 += __shfl_xor_sync(0xffffffffu, s1, 1);
        s1 += __shfl_xor_sync(0xffffffffu, s1, 2);
        lrow0 = lrow0 * a0 + s0;
        lrow1 = lrow1 * a1 + s1;
#pragma unroll
        for (int nj = 0; nj < 8; nj++) {
            cO[nj][0] *= a0; cO[nj][1] *= a0;
            cO[nj][2] *= a1; cO[nj][3] *= a1;
        }

        // ---- Store P (tf32) to smem ----
#pragma unroll
        for (int nj = 0; nj < 16; nj++) {
            int col = nj * 8 + 2 * tig;
            uint2 p0 = make_uint2(f2tf32(cS[nj][0]), f2tf32(cS[nj][1]));
            *(uint2*)&Ps[(r0 + gid) * PPAD + col] = p0;
            uint2 p1 = make_uint2(f2tf32(cS[nj][2]), f2tf32(cS[nj][3]));
            *(uint2*)&Ps[(r0 + gid + 8) * PPAD + col] = p1;
        }
        __syncthreads();

        // ---- O += P @ V : 16 rows x 64 dims (8 n-tiles), 16 k-steps ----
#pragma unroll
        for (int ks = 0; ks < 16; ks++) {
            uint32_t pa[4];
            int abase = (r0 + gid) * PPAD + ks * 8 + tig;
            pa[0] = Ps[abase];
            pa[1] = Ps[abase + 8 * PPAD];
            pa[2] = Ps[abase + 4];
            pa[3] = Ps[abase + 8 * PPAD + 4];
#pragma unroll
            for (int nj = 0; nj < 8; nj++) {
                uint32_t bb[2];
                int bbase = (ks * 8 + tig) * VPAD + nj * 8 + gid;
                bb[0] = Vs[bbase];
                bb[1] = Vs[bbase + 4 * VPAD];
                mma_tf32(cO[nj], pa, bb);
            }
        }
    }

    // ---- Epilogue ----
    float inv0 = 1.0f / lrow0, inv1 = 1.0f / lrow1;
    long rowA = (long)(b * TT + qb * 128 + r0 + gid) * 1024 + h * 64;
    long rowB = rowA + 8 * 1024;
#pragma unroll
    for (int nj = 0; nj < 8; nj++) {
        int col = nj * 8 + 2 * tig;
        *(float2*)(y + rowA + col) = make_float2(cO[nj][0] * inv0, cO[nj][1] * inv0);
        *(float2*)(y + rowB + col) = make_float2(cO[nj][2] * inv1, cO[nj][3] * inv1);
    }
}

// ---------------------------------------------------------------------------
extern "C" void kernel_launch(void* const* d_in, const int* in_sizes, int n_in,
                              void* d_out, int out_size) {
    const float* x      = (const float*)d_in[0];
    const float* cosb   = (const float*)d_in[1];
    const float* sinb   = (const float*)d_in[2];
    const float* W_attn = (const float*)d_in[3];
    const float* b_attn = (const float*)d_in[4];
    const float* W_proj = (const float*)d_in[5];
    const float* b_proj = (const float*)d_in[6];
    float* out = (float*)d_out;

    float *qkv, *y;
    cudaGetSymbolAddress((void**)&qkv, g_qkv);
    cudaGetSymbolAddress((void**)&y, g_y);

    // 1) QKV GEMM (TF32): [4096,1024] @ [1024,3072] + bias
    tf32_gemm_bias<<<dim3(3072 / 128, 4096 / 128), 256>>>(x, W_attn, b_attn, qkv, 4096, 3072, 1024);

    // 2) per-head RMSNorm + RoPE on q,k (in place)
    norm_rope_kernel<<<2 * TT, 256>>>(qkv, cosb, sinb);

    // 3) causal flash attention (TF32 tensor cores)
    cudaFuncSetAttribute(attn_tf32_kernel, cudaFuncAttributeMaxDynamicSharedMemorySize, ATT_SMEM);
    attn_tf32_kernel<<<dim3(TT / 128, 16, 2), 256, ATT_SMEM>>>(qkv, y);

    // 4) output projection (TF32): [4096,1024] @ [1024,1024] + bias
    tf32_gemm_bias<<<dim3(1024 / 128, 4096 / 128), 256>>>(y, W_proj, b_proj, out, 4096, 1024, 1024);
}

// round 6
// speedup vs baseline: 6.3981x; 1.0784x over previous
#include <cuda_runtime.h>
#include <cstdint>

// Problem constants: B=2, T=2048, C=1024, H=16, D=64
#define TT 2048

// Scratch (allocation-free rule: __device__ globals)
__device__ float g_qkv[2 * 2048 * 3 * 1024];  // [B,T,3,H,D]
__device__ float g_y[2 * 2048 * 1024];        // [B,T,H,D]

__device__ __forceinline__ uint32_t f2tf32(float f) {
    uint32_t r;
    asm("cvt.rna.tf32.f32 %0, %1;" : "=r"(r) : "f"(f));
    return r;
}

__device__ __forceinline__ void mma_tf32(float* c, const uint32_t* a, const uint32_t* b) {
    asm volatile(
        "mma.sync.aligned.m16n8k8.row.col.f32.tf32.tf32.f32 "
        "{%0,%1,%2,%3}, {%4,%5,%6,%7}, {%8,%9}, {%0,%1,%2,%3};\n"
        : "+f"(c[0]), "+f"(c[1]), "+f"(c[2]), "+f"(c[3])
        : "r"(a[0]), "r"(a[1]), "r"(a[2]), "r"(a[3]), "r"(b[0]), "r"(b[1]));
}

// ---------------------------------------------------------------------------
// TF32 tensor-core GEMM with bias, 2-stage smem double buffer.
// 128x128 CTA tile, BK=16, 8 warps (4x2), warp tile 32x64 = 2x8 m16n8k8.
// ---------------------------------------------------------------------------
#define PADK 20
#define PADN 136

__global__ __launch_bounds__(256, 2)
void tf32_gemm_bias(const float* __restrict__ A, const float* __restrict__ Bw,
                    const float* __restrict__ bias, float* __restrict__ Cout,
                    int M, int N, int K) {
    __shared__ uint32_t As[2][128 * PADK];
    __shared__ uint32_t Bs[2][16 * PADN];

    const int tid = threadIdx.x;
    const int lane = tid & 31;
    const int warp = tid >> 5;
    const int gid = lane >> 2;
    const int tig = lane & 3;
    const int wm = warp >> 1;
    const int wn = warp & 1;
    const int m0w = wm * 32;
    const int n0w = wn * 64;
    const int br = blockIdx.y * 128;
    const int bc = blockIdx.x * 128;

    const int arow = tid >> 2;
    const int akc  = (tid & 3) * 4;
    const int bkr  = tid >> 5;
    const int bnc  = (tid & 31) * 4;

    const float* Ap0 = A + (long)(br + arow) * K + akc;
    const float* Ap1 = A + (long)(br + arow + 64) * K + akc;
    const float* Bp0 = Bw + (long)bkr * N + bc + bnc;
    const float* Bp1 = Bw + (long)(bkr + 8) * N + bc + bnc;

    float c[2][8][4];
#pragma unroll
    for (int mi = 0; mi < 2; mi++)
#pragma unroll
        for (int nj = 0; nj < 8; nj++)
#pragma unroll
            for (int e = 0; e < 4; e++) c[mi][nj][e] = 0.f;

    // Prologue: load tile 0, store to stage 0
    float4 ag0 = *(const float4*)(Ap0);
    float4 ag1 = *(const float4*)(Ap1);
    float4 bg0 = *(const float4*)(Bp0);
    float4 bg1 = *(const float4*)(Bp1);
    {
        uint4 s;
        s.x = f2tf32(ag0.x); s.y = f2tf32(ag0.y); s.z = f2tf32(ag0.z); s.w = f2tf32(ag0.w);
        *(uint4*)&As[0][arow * PADK + akc] = s;
        s.x = f2tf32(ag1.x); s.y = f2tf32(ag1.y); s.z = f2tf32(ag1.z); s.w = f2tf32(ag1.w);
        *(uint4*)&As[0][(arow + 64) * PADK + akc] = s;
        s.x = f2tf32(bg0.x); s.y = f2tf32(bg0.y); s.z = f2tf32(bg0.z); s.w = f2tf32(bg0.w);
        *(uint4*)&Bs[0][bkr * PADN + bnc] = s;
        s.x = f2tf32(bg1.x); s.y = f2tf32(bg1.y); s.z = f2tf32(bg1.z); s.w = f2tf32(bg1.w);
        *(uint4*)&Bs[0][(bkr + 8) * PADN + bnc] = s;
    }
    __syncthreads();

    int st = 0;
    for (int k0 = 0; k0 < K; k0 += 16) {
        const bool hasNext = (k0 + 16 < K);
        if (hasNext) {  // global prefetch overlaps the math below
            ag0 = *(const float4*)(Ap0 + k0 + 16);
            ag1 = *(const float4*)(Ap1 + k0 + 16);
            bg0 = *(const float4*)(Bp0 + (long)(k0 + 16) * N);
            bg1 = *(const float4*)(Bp1 + (long)(k0 + 16) * N);
        }

        // Math on stage st
#pragma unroll
        for (int ks = 0; ks < 16; ks += 8) {
            uint32_t a[2][4];
#pragma unroll
            for (int mi = 0; mi < 2; mi++) {
                int base = (m0w + mi * 16 + gid) * PADK + ks + tig;
                a[mi][0] = As[st][base];
                a[mi][1] = As[st][base + 8 * PADK];
                a[mi][2] = As[st][base + 4];
                a[mi][3] = As[st][base + 8 * PADK + 4];
            }
            uint32_t b[8][2];
#pragma unroll
            for (int nj = 0; nj < 8; nj++) {
                int base = (ks + tig) * PADN + n0w + nj * 8 + gid;
                b[nj][0] = Bs[st][base];
                b[nj][1] = Bs[st][base + 4 * PADN];
            }
#pragma unroll
            for (int mi = 0; mi < 2; mi++)
#pragma unroll
                for (int nj = 0; nj < 8; nj++)
                    mma_tf32(c[mi][nj], a[mi], b[nj]);
        }

        // Store prefetched tile into the other stage
        if (hasNext) {
            uint4 s;
            s.x = f2tf32(ag0.x); s.y = f2tf32(ag0.y); s.z = f2tf32(ag0.z); s.w = f2tf32(ag0.w);
            *(uint4*)&As[st ^ 1][arow * PADK + akc] = s;
            s.x = f2tf32(ag1.x); s.y = f2tf32(ag1.y); s.z = f2tf32(ag1.z); s.w = f2tf32(ag1.w);
            *(uint4*)&As[st ^ 1][(arow + 64) * PADK + akc] = s;
            s.x = f2tf32(bg0.x); s.y = f2tf32(bg0.y); s.z = f2tf32(bg0.z); s.w = f2tf32(bg0.w);
            *(uint4*)&Bs[st ^ 1][bkr * PADN + bnc] = s;
            s.x = f2tf32(bg1.x); s.y = f2tf32(bg1.y); s.z = f2tf32(bg1.z); s.w = f2tf32(bg1.w);
            *(uint4*)&Bs[st ^ 1][(bkr + 8) * PADN + bnc] = s;
        }
        __syncthreads();
        st ^= 1;
    }

#pragma unroll
    for (int mi = 0; mi < 2; mi++) {
        int row = br + m0w + mi * 16 + gid;
#pragma unroll
        for (int nj = 0; nj < 8; nj++) {
            int col = bc + n0w + nj * 8 + tig * 2;
            float2 bb = *(const float2*)(bias + col);
            float2 o0 = make_float2(c[mi][nj][0] + bb.x, c[mi][nj][1] + bb.y);
            float2 o1 = make_float2(c[mi][nj][2] + bb.x, c[mi][nj][3] + bb.y);
            *(float2*)(Cout + (long)row * N + col) = o0;
            *(float2*)(Cout + (long)(row + 8) * N + col) = o1;
        }
    }
}

// ---------------------------------------------------------------------------
// Fused per-head RMSNorm + RoPE on q and k slots of g_qkv (in place).
// ---------------------------------------------------------------------------
__global__ __launch_bounds__(256)
void norm_rope_kernel(float* __restrict__ qkv,
                      const float* __restrict__ cosb,
                      const float* __restrict__ sinb) {
    __shared__ float qn[1024];
    __shared__ float kn[1024];
    const int bt = blockIdx.x;
    const int t = bt & (TT - 1);
    const int tid = threadIdx.x;
    float* qrow = qkv + (long)bt * 3072;
    float* krow = qrow + 1024;

    float4 qv = *(const float4*)(qrow + tid * 4);
    float4 kv = *(const float4*)(krow + tid * 4);
    float qs = qv.x * qv.x + qv.y * qv.y + qv.z * qv.z + qv.w * qv.w;
    float ks = kv.x * kv.x + kv.y * kv.y + kv.z * kv.z + kv.w * kv.w;
#pragma unroll
    for (int o = 8; o > 0; o >>= 1) {
        qs += __shfl_xor_sync(0xffffffffu, qs, o);
        ks += __shfl_xor_sync(0xffffffffu, ks, o);
    }
    const float qsc = rsqrtf(qs * (1.f / 64.f) + 1.1920929e-07f);
    const float ksc = rsqrtf(ks * (1.f / 64.f) + 1.1920929e-07f);
    float4 qn4 = make_float4(qv.x * qsc, qv.y * qsc, qv.z * qsc, qv.w * qsc);
    float4 kn4 = make_float4(kv.x * ksc, kv.y * ksc, kv.z * ksc, kv.w * ksc);
    *(float4*)&qn[tid * 4] = qn4;
    *(float4*)&kn[tid * 4] = kn4;
    __syncthreads();

    const int i = tid * 4;
    const int d = i & 63;
    const int base = i - d;
    float4 cv = *(const float4*)(cosb + t * 64 + d);
    float4 sv = *(const float4*)(sinb + t * 64 + d);
    float4 rq, rk;
    if (d < 32) {
        float4 pq = *(const float4*)&qn[base + d + 32];
        float4 pk = *(const float4*)&kn[base + d + 32];
        rq = make_float4(-pq.x, -pq.y, -pq.z, -pq.w);
        rk = make_float4(-pk.x, -pk.y, -pk.z, -pk.w);
    } else {
        rq = *(const float4*)&qn[base + d - 32];
        rk = *(const float4*)&kn[base + d - 32];
    }
    float4 oq, ok;
    oq.x = qn4.x * cv.x + rq.x * sv.x;  oq.y = qn4.y * cv.y + rq.y * sv.y;
    oq.z = qn4.z * cv.z + rq.z * sv.z;  oq.w = qn4.w * cv.w + rq.w * sv.w;
    ok.x = kn4.x * cv.x + rk.x * sv.x;  ok.y = kn4.y * cv.y + rk.y * sv.y;
    ok.z = kn4.z * cv.z + rk.z * sv.z;  ok.w = kn4.w * cv.w + rk.w * sv.w;
    *(float4*)(qrow + i) = oq;
    *(float4*)(krow + i) = ok;
}

// ---------------------------------------------------------------------------
// TF32 flash attention: BQ=128 (rows/CTA), BKV=64 (kv/tile), 8 warps,
// warp = 16 rows x 64 kv cols. Small cS -> ~125 regs -> 2 CTAs/SM.
// ---------------------------------------------------------------------------
#define KPAD 68    // K frag lanes: 4*gid + tig -> all 32 banks
#define VPAD 72    // V frag lanes: 8*tig + gid -> all 32 banks
#define PPAD 68    // P frag loads conflict-free; stores 2-way (cheap)
#define ATT_SMEM ((64 * KPAD + 64 * VPAD + 128 * PPAD) * 4)

__global__ __launch_bounds__(256, 2)
void attn_tf32_kernel(const float* __restrict__ qkv, float* __restrict__ y) {
    extern __shared__ uint32_t smu[];
    uint32_t* Ks = smu;                 // [64][KPAD]
    uint32_t* Vs = Ks + 64 * KPAD;      // [64][VPAD]
    uint32_t* Ps = Vs + 64 * VPAD;      // [128][PPAD]; also Q staging

    const int qb = (int)(gridDim.x - 1) - (int)blockIdx.x;  // heavy CTAs first
    const int h = blockIdx.y, b = blockIdx.z;
    const int tid = threadIdx.x;
    const int lane = tid & 31, warp = tid >> 5;
    const int gid = lane >> 2, tig = lane & 3;
    const int r0 = warp * 16;

    // ---- Stage Q (scaled, tf32) into Ps, then load A-fragments ----
    {
        const int row = tid >> 1;
        const int dh = (tid & 1) * 32;
        const float* src = qkv + ((long)(b * TT + qb * 128 + row) * 3) * 1024 + h * 64 + dh;
#pragma unroll
        for (int j = 0; j < 8; j++) {
            float4 v = *(const float4*)(src + j * 4);
            uint4 s;
            s.x = f2tf32(v.x * 0.125f); s.y = f2tf32(v.y * 0.125f);
            s.z = f2tf32(v.z * 0.125f); s.w = f2tf32(v.w * 0.125f);
            *(uint4*)&Ps[row * PPAD + dh + j * 4] = s;
        }
    }
    __syncthreads();
    uint32_t qa[8][4];
#pragma unroll
    for (int ks = 0; ks < 8; ks++) {
        int base = (r0 + gid) * PPAD + ks * 8 + tig;
        qa[ks][0] = Ps[base];
        qa[ks][1] = Ps[base + 8 * PPAD];
        qa[ks][2] = Ps[base + 4];
        qa[ks][3] = Ps[base + 8 * PPAD + 4];
    }

    float cO[8][4];
#pragma unroll
    for (int nj = 0; nj < 8; nj++)
#pragma unroll
        for (int e = 0; e < 4; e++) cO[nj][e] = 0.f;
    float mrow0 = -3.0e38f, mrow1 = -3.0e38f, lrow0 = 0.f, lrow1 = 0.f;

    const int nkv = 2 * (qb + 1);
    for (int kb = 0; kb < nkv; kb++) {
        __syncthreads();  // prev-iter S/PV readers done with Ks/Vs/Ps
        // ---- Load K, V tiles (64 rows, tf32) ----
        {
            const int row = tid >> 2;
            const int dh = (tid & 3) * 16;
            const float* ksrc = qkv + ((long)(b * TT + kb * 64 + row) * 3 + 1) * 1024 + h * 64 + dh;
            const float* vsrc = qkv + ((long)(b * TT + kb * 64 + row) * 3 + 2) * 1024 + h * 64 + dh;
#pragma unroll
            for (int j = 0; j < 4; j++) {
                float4 v = *(const float4*)(ksrc + j * 4);
                uint4 s;
                s.x = f2tf32(v.x); s.y = f2tf32(v.y); s.z = f2tf32(v.z); s.w = f2tf32(v.w);
                *(uint4*)&Ks[row * KPAD + dh + j * 4] = s;
                v = *(const float4*)(vsrc + j * 4);
                s.x = f2tf32(v.x); s.y = f2tf32(v.y); s.z = f2tf32(v.z); s.w = f2tf32(v.w);
                *(uint4*)&Vs[row * VPAD + dh + j * 4] = s;
            }
        }
        __syncthreads();

        // ---- S = Q @ K^T : warp computes 16 rows x 64 cols (8 n-tiles) ----
        float cS[8][4];
#pragma unroll
        for (int nj = 0; nj < 8; nj++)
#pragma unroll
            for (int e = 0; e < 4; e++) cS[nj][e] = 0.f;

#pragma unroll
        for (int ks = 0; ks < 8; ks++) {
#pragma unroll
            for (int nj = 0; nj < 8; nj++) {
                uint32_t bb[2];
                int base = (nj * 8 + gid) * KPAD + ks * 8 + tig;
                bb[0] = Ks[base];
                bb[1] = Ks[base + 4];
                mma_tf32(cS[nj], qa[ks], bb);
            }
        }

        if (kb >= 2 * qb) {  // tiles intersecting the causal diagonal
            int rA = qb * 128 + r0 + gid;
            int rB = rA + 8;
#pragma unroll
            for (int nj = 0; nj < 8; nj++) {
                int col = kb * 64 + nj * 8 + 2 * tig;
                if (col     > rA) cS[nj][0] = -3.0e38f;
                if (col + 1 > rA) cS[nj][1] = -3.0e38f;
                if (col     > rB) cS[nj][2] = -3.0e38f;
                if (col + 1 > rB) cS[nj][3] = -3.0e38f;
            }
        }

        // ---- Online softmax (2 rows per thread; reduce over 4 tig lanes) ----
        float mx0 = -3.0e38f, mx1 = -3.0e38f;
#pragma unroll
        for (int nj = 0; nj < 8; nj++) {
            mx0 = fmaxf(mx0, fmaxf(cS[nj][0], cS[nj][1]));
            mx1 = fmaxf(mx1, fmaxf(cS[nj][2], cS[nj][3]));
        }
        mx0 = fmaxf(mx0, __shfl_xor_sync(0xffffffffu, mx0, 1));
        mx0 = fmaxf(mx0, __shfl_xor_sync(0xffffffffu, mx0, 2));
        mx1 = fmaxf(mx1, __shfl_xor_sync(0xffffffffu, mx1, 1));
        mx1 = fmaxf(mx1, __shfl_xor_sync(0xffffffffu, mx1, 2));
        float mn0 = fmaxf(mrow0, mx0), mn1 = fmaxf(mrow1, mx1);
        float a0 = __expf(mrow0 - mn0), a1 = __expf(mrow1 - mn1);
        mrow0 = mn0; mrow1 = mn1;
        float s0 = 0.f, s1 = 0.f;
#pragma unroll
        for (int nj = 0; nj < 8; nj++) {
            cS[nj][0] = __expf(cS[nj][0] - mn0); s0 += cS[nj][0];
            cS[nj][1] = __expf(cS[nj][1] - mn0); s0 += cS[nj][1];
            cS[nj][2] = __expf(cS[nj][2] - mn1); s1 += cS[nj][2];
            cS[nj][3] = __expf(cS[nj][3] - mn1); s1 += cS[nj][3];
        }
        s0 += __shfl_xor_sync(0xffffffffu, s0, 1);
        s0 += __shfl_xor_sync(0xffffffffu, s0, 2);
        s1 += __shfl_xor_sync(0xffffffffu, s1, 1);
        s1 += __shfl_xor_sync(0xffffffffu, s1, 2);
        lrow0 = lrow0 * a0 + s0;
        lrow1 = lrow1 * a1 + s1;
#pragma unroll
        for (int nj = 0; nj < 8; nj++) {
            cO[nj][0] *= a0; cO[nj][1] *= a0;
            cO[nj][2] *= a1; cO[nj][3] *= a1;
        }

        // ---- Store P (tf32); each warp touches only its own 16 rows ----
#pragma unroll
        for (int nj = 0; nj < 8; nj++) {
            int col = nj * 8 + 2 * tig;
            uint2 p0 = make_uint2(f2tf32(cS[nj][0]), f2tf32(cS[nj][1]));
            *(uint2*)&Ps[(r0 + gid) * PPAD + col] = p0;
            uint2 p1 = make_uint2(f2tf32(cS[nj][2]), f2tf32(cS[nj][3]));
            *(uint2*)&Ps[(r0 + gid + 8) * PPAD + col] = p1;
        }
        __syncwarp();  // same-warp visibility only; no CTA barrier needed

        // ---- O += P @ V : 16 rows x 64 dims (8 n-tiles), 8 k-steps ----
#pragma unroll
        for (int ks = 0; ks < 8; ks++) {
            uint32_t pa[4];
            int abase = (r0 + gid) * PPAD + ks * 8 + tig;
            pa[0] = Ps[abase];
            pa[1] = Ps[abase + 8 * PPAD];
            pa[2] = Ps[abase + 4];
            pa[3] = Ps[abase + 8 * PPAD + 4];
#pragma unroll
            for (int nj = 0; nj < 8; nj++) {
                uint32_t bb[2];
                int bbase = (ks * 8 + tig) * VPAD + nj * 8 + gid;
                bb[0] = Vs[bbase];
                bb[1] = Vs[bbase + 4 * VPAD];
                mma_tf32(cO[nj], pa, bb);
            }
        }
    }

    // ---- Epilogue ----
    float inv0 = 1.0f / lrow0, inv1 = 1.0f / lrow1;
    long rowA = (long)(b * TT + qb * 128 + r0 + gid) * 1024 + h * 64;
    long rowB = rowA + 8 * 1024;
#pragma unroll
    for (int nj = 0; nj < 8; nj++) {
        int col = nj * 8 + 2 * tig;
        *(float2*)(y + rowA + col) = make_float2(cO[nj][0] * inv0, cO[nj][1] * inv0);
        *(float2*)(y + rowB + col) = make_float2(cO[nj][2] * inv1, cO[nj][3] * inv1);
    }
}

// ---------------------------------------------------------------------------
extern "C" void kernel_launch(void* const* d_in, const int* in_sizes, int n_in,
                              void* d_out, int out_size) {
    const float* x      = (const float*)d_in[0];
    const float* cosb   = (const float*)d_in[1];
    const float* sinb   = (const float*)d_in[2];
    const float* W_attn = (const float*)d_in[3];
    const float* b_attn = (const float*)d_in[4];
    const float* W_proj = (const float*)d_in[5];
    const float* b_proj = (const float*)d_in[6];
    float* out = (float*)d_out;

    float *qkv, *y;
    cudaGetSymbolAddress((void**)&qkv, g_qkv);
    cudaGetSymbolAddress((void**)&y, g_y);

    // 1) QKV GEMM (TF32, double-buffered): [4096,1024] @ [1024,3072] + bias
    tf32_gemm_bias<<<dim3(3072 / 128, 4096 / 128), 256>>>(x, W_attn, b_attn, qkv, 4096, 3072, 1024);

    // 2) per-head RMSNorm + RoPE on q,k (in place)
    norm_rope_kernel<<<2 * TT, 256>>>(qkv, cosb, sinb);

    // 3) causal flash attention (TF32, BKV=64, 2 CTAs/SM)
    cudaFuncSetAttribute(attn_tf32_kernel, cudaFuncAttributeMaxDynamicSharedMemorySize, ATT_SMEM);
    attn_tf32_kernel<<<dim3(TT / 128, 16, 2), 256, ATT_SMEM>>>(qkv, y);

    // 4) output projection (TF32, double-buffered): [4096,1024] @ [1024,1024] + bias
    tf32_gemm_bias<<<dim3(1024 / 128, 4096 / 128), 256>>>(y, W_proj, b_proj, out, 4096, 1024, 1024);
}